// round 1
// baseline (speedup 1.0000x reference)
#include <cuda_runtime.h>
#include <math.h>

#define BB 4
#define SS 2048
#define DD 1024
#define HH 16
#define EE 64

// Scratch (device globals: allocation-free per harness rules)
__device__ float g_Q[BB*HH*SS*EE];
__device__ float g_K[BB*HH*SS*EE];
__device__ float g_V[BB*HH*SS*EE];
__device__ float g_ctx[BB*SS*HH*EE];

// ---------------------------------------------------------------------------
// Projection GEMM: out[b,h,s,e] = sum_d A[(b,s),d] * W[h,d,e] + bias[h,e]
// A: [M=8192, K=1024] row-major, W: [H,D,E], bias: [H,E]
// Tile 128x128, BK=8, 256 threads, 8x8 microtile (split 4+4 across 64 offset)
// which: 0 -> g_Q, 1 -> g_K, 2 -> g_V
// ---------------------------------------------------------------------------
__global__ __launch_bounds__(256, 2)
void proj_gemm(const float* __restrict__ A, const float* __restrict__ W,
               const float* __restrict__ bias, int which)
{
    const int K = DD;
    __shared__ float As[8][128];
    __shared__ float Bs[8][128];

    float* outp = (which == 0) ? g_Q : (which == 1) ? g_K : g_V;

    int tid = threadIdx.x;
    int tx = tid & 15, ty = tid >> 4;
    int m0 = blockIdx.y * 128, n0 = blockIdx.x * 128;

    int arow = tid >> 1, acol = (tid & 1) * 4;
    int brow = tid >> 5, bcol = (tid & 31) * 4;

    float acc[8][8];
#pragma unroll
    for (int i = 0; i < 8; i++)
#pragma unroll
        for (int j = 0; j < 8; j++) acc[i][j] = 0.f;

    const float* Aptr = A + (m0 + arow) * K + acol;

    for (int k0 = 0; k0 < K; k0 += 8) {
        float4 av = *(const float4*)(Aptr + k0);
        int n = n0 + bcol;
        float4 bv = *(const float4*)&W[((n >> 6) * K + (k0 + brow)) * EE + (n & 63)];
        __syncthreads();
        As[acol + 0][arow] = av.x;
        As[acol + 1][arow] = av.y;
        As[acol + 2][arow] = av.z;
        As[acol + 3][arow] = av.w;
        *(float4*)&Bs[brow][bcol] = bv;
        __syncthreads();
#pragma unroll
        for (int kk = 0; kk < 8; kk++) {
            float a[8], b[8];
            *(float4*)&a[0] = *(float4*)&As[kk][ty * 4];
            *(float4*)&a[4] = *(float4*)&As[kk][ty * 4 + 64];
            *(float4*)&b[0] = *(float4*)&Bs[kk][tx * 4];
            *(float4*)&b[4] = *(float4*)&Bs[kk][tx * 4 + 64];
#pragma unroll
            for (int i = 0; i < 8; i++)
#pragma unroll
                for (int j = 0; j < 8; j++) acc[i][j] += a[i] * b[j];
        }
    }

#pragma unroll
    for (int i = 0; i < 8; i++) {
        int m = m0 + ty * 4 + (i & 3) + (i >> 2) * 64;
        int bb = m >> 11;          // /2048
        int s  = m & 2047;
#pragma unroll
        for (int jj = 0; jj < 2; jj++) {
            int n = n0 + tx * 4 + jj * 64;
            int h = n >> 6, e = n & 63;
            float4 bvv = *(const float4*)&bias[n];
            float4 o;
            o.x = acc[i][jj * 4 + 0] + bvv.x;
            o.y = acc[i][jj * 4 + 1] + bvv.y;
            o.z = acc[i][jj * 4 + 2] + bvv.z;
            o.w = acc[i][jj * 4 + 3] + bvv.w;
            *(float4*)&outp[(((bb * HH + h) * SS) + s) * EE + e] = o;
        }
    }
}

// ---------------------------------------------------------------------------
// Output GEMM: d_out[(b,s),n] = sum_k g_ctx[(b,s),k] * Wo[k,n] + bo[n]
// ---------------------------------------------------------------------------
__global__ __launch_bounds__(256, 2)
void out_gemm(const float* __restrict__ Wo, const float* __restrict__ bo,
              float* __restrict__ out)
{
    const int K = HH * EE;  // 1024
    const int N = DD;       // 1024
    __shared__ float As[8][128];
    __shared__ float Bs[8][128];

    int tid = threadIdx.x;
    int tx = tid & 15, ty = tid >> 4;
    int m0 = blockIdx.y * 128, n0 = blockIdx.x * 128;

    int arow = tid >> 1, acol = (tid & 1) * 4;
    int brow = tid >> 5, bcol = (tid & 31) * 4;

    float acc[8][8];
#pragma unroll
    for (int i = 0; i < 8; i++)
#pragma unroll
        for (int j = 0; j < 8; j++) acc[i][j] = 0.f;

    const float* Aptr = g_ctx + (m0 + arow) * K + acol;

    for (int k0 = 0; k0 < K; k0 += 8) {
        float4 av = *(const float4*)(Aptr + k0);
        float4 bv = *(const float4*)&Wo[(k0 + brow) * N + n0 + bcol];
        __syncthreads();
        As[acol + 0][arow] = av.x;
        As[acol + 1][arow] = av.y;
        As[acol + 2][arow] = av.z;
        As[acol + 3][arow] = av.w;
        *(float4*)&Bs[brow][bcol] = bv;
        __syncthreads();
#pragma unroll
        for (int kk = 0; kk < 8; kk++) {
            float a[8], b[8];
            *(float4*)&a[0] = *(float4*)&As[kk][ty * 4];
            *(float4*)&a[4] = *(float4*)&As[kk][ty * 4 + 64];
            *(float4*)&b[0] = *(float4*)&Bs[kk][tx * 4];
            *(float4*)&b[4] = *(float4*)&Bs[kk][tx * 4 + 64];
#pragma unroll
            for (int i = 0; i < 8; i++)
#pragma unroll
                for (int j = 0; j < 8; j++) acc[i][j] += a[i] * b[j];
        }
    }

#pragma unroll
    for (int i = 0; i < 8; i++) {
        int m = m0 + ty * 4 + (i & 3) + (i >> 2) * 64;
#pragma unroll
        for (int jj = 0; jj < 2; jj++) {
            int n = n0 + tx * 4 + jj * 64;
            float4 bvv = *(const float4*)&bo[n];
            float4 o;
            o.x = acc[i][jj * 4 + 0] + bvv.x;
            o.y = acc[i][jj * 4 + 1] + bvv.y;
            o.z = acc[i][jj * 4 + 2] + bvv.z;
            o.w = acc[i][jj * 4 + 3] + bvv.w;
            *(float4*)&out[m * N + n] = o;
        }
    }
}

// ---------------------------------------------------------------------------
// Flash attention per (b,h): 64x64 tiles, online softmax, fused head gate.
// block = 256 threads = 16x16; thread (ty,tx): rows ty*4+i, cols tx+16*j
// (column mapping keeps all shared loads broadcast or stride-1 -> no bank
//  conflicts). Writes g_ctx in [B,S,H*E] layout.
// ---------------------------------------------------------------------------
#define ATTN_SMEM_FLOATS (4 * 64 * 65)

__global__ __launch_bounds__(256)
void attn_kernel(const float* __restrict__ sel)
{
    extern __shared__ float sm[];
    float* Qs = sm;
    float* Ks = sm + 64 * 65;
    float* Vs = sm + 2 * 64 * 65;
    float* Ps = sm + 3 * 64 * 65;

    int tid = threadIdx.x;
    int tx = tid & 15, ty = tid >> 4;
    int bh = blockIdx.y;
    int b = bh >> 4, h = bh & 15;
    int qt = blockIdx.x;

    // head weight = softmax(sel)[h], computed redundantly (16 cached loads)
    float hm = -1e30f;
#pragma unroll
    for (int i = 0; i < HH; i++) hm = fmaxf(hm, sel[i]);
    float hsum = 0.f;
#pragma unroll
    for (int i = 0; i < HH; i++) hsum += __expf(sel[i] - hm);
    float hw = __expf(sel[h] - hm) / hsum;

    const float scale = 0.125f;  // 1/sqrt(64)
    const float* Qg = g_Q + ((size_t)(b * HH + h) * SS + qt * 64) * EE;
    const float* Kg = g_K + ((size_t)(b * HH + h) * SS) * EE;
    const float* Vg = g_V + ((size_t)(b * HH + h) * SS) * EE;

    // load Q tile [64,64]
#pragma unroll
    for (int l = 0; l < 4; l++) {
        int p = tid + l * 256;          // float4 index 0..1023
        int r = p >> 4, c4 = (p & 15) * 4;
        float4 v = *(const float4*)(Qg + r * EE + c4);
        Qs[r * 65 + c4 + 0] = v.x;
        Qs[r * 65 + c4 + 1] = v.y;
        Qs[r * 65 + c4 + 2] = v.z;
        Qs[r * 65 + c4 + 3] = v.w;
    }

    float m_i[4], l_i[4], acc[4][4];
#pragma unroll
    for (int i = 0; i < 4; i++) {
        m_i[i] = -1e30f;
        l_i[i] = 0.f;
#pragma unroll
        for (int j = 0; j < 4; j++) acc[i][j] = 0.f;
    }

    for (int kt = 0; kt < SS / 64; kt++) {
        __syncthreads();  // prev iteration's P/V reads done
        // load K,V tiles
#pragma unroll
        for (int l = 0; l < 4; l++) {
            int p = tid + l * 256;
            int r = p >> 4, c4 = (p & 15) * 4;
            const float* kp = Kg + (size_t)(kt * 64 + r) * EE + c4;
            const float* vp = Vg + (size_t)(kt * 64 + r) * EE + c4;
            float4 kv = *(const float4*)kp;
            float4 vv = *(const float4*)vp;
            Ks[r * 65 + c4 + 0] = kv.x;
            Ks[r * 65 + c4 + 1] = kv.y;
            Ks[r * 65 + c4 + 2] = kv.z;
            Ks[r * 65 + c4 + 3] = kv.w;
            Vs[r * 65 + c4 + 0] = vv.x;
            Vs[r * 65 + c4 + 1] = vv.y;
            Vs[r * 65 + c4 + 2] = vv.z;
            Vs[r * 65 + c4 + 3] = vv.w;
        }
        __syncthreads();

        // scores S = Q K^T
        float s[4][4];
#pragma unroll
        for (int i = 0; i < 4; i++)
#pragma unroll
            for (int j = 0; j < 4; j++) s[i][j] = 0.f;

#pragma unroll 4
        for (int k = 0; k < 64; k++) {
            float q[4], kk_[4];
#pragma unroll
            for (int i = 0; i < 4; i++) q[i] = Qs[(ty * 4 + i) * 65 + k];       // broadcast
#pragma unroll
            for (int j = 0; j < 4; j++) kk_[j] = Ks[(tx + 16 * j) * 65 + k];    // stride-65: conflict-free
#pragma unroll
            for (int i = 0; i < 4; i++)
#pragma unroll
                for (int j = 0; j < 4; j++) s[i][j] += q[i] * kk_[j];
        }

        // online softmax update (row stats reduced over 16 lanes sharing ty)
#pragma unroll
        for (int i = 0; i < 4; i++) {
            float tm = -1e30f;
#pragma unroll
            for (int j = 0; j < 4; j++) {
                s[i][j] *= scale;
                tm = fmaxf(tm, s[i][j]);
            }
#pragma unroll
            for (int o = 1; o < 16; o <<= 1)
                tm = fmaxf(tm, __shfl_xor_sync(0xffffffffu, tm, o));
            float nm = fmaxf(m_i[i], tm);
            float alpha = __expf(m_i[i] - nm);
            m_i[i] = nm;
            float rs = 0.f;
#pragma unroll
            for (int j = 0; j < 4; j++) {
                s[i][j] = __expf(s[i][j] - nm);
                rs += s[i][j];
            }
#pragma unroll
            for (int o = 1; o < 16; o <<= 1)
                rs += __shfl_xor_sync(0xffffffffu, rs, o);
            l_i[i] = l_i[i] * alpha + rs;
#pragma unroll
            for (int j = 0; j < 4; j++) {
                acc[i][j] *= alpha;
                Ps[(ty * 4 + i) * 65 + tx + 16 * j] = s[i][j];
            }
        }
        __syncthreads();

        // O += P V
#pragma unroll 4
        for (int c = 0; c < 64; c++) {
            float pv[4], vv[4];
#pragma unroll
            for (int i = 0; i < 4; i++) pv[i] = Ps[(ty * 4 + i) * 65 + c];      // broadcast
#pragma unroll
            for (int j = 0; j < 4; j++) vv[j] = Vs[c * 65 + tx + 16 * j];       // stride-1
#pragma unroll
            for (int i = 0; i < 4; i++)
#pragma unroll
                for (int j = 0; j < 4; j++) acc[i][j] += pv[i] * vv[j];
        }
    }

    // epilogue: normalize, gate by head weight, write ctx [B,S,H*E]
#pragma unroll
    for (int i = 0; i < 4; i++) {
        int row = qt * 64 + ty * 4 + i;
        float inv = hw / l_i[i];
#pragma unroll
        for (int j = 0; j < 4; j++) {
            int e = tx + 16 * j;
            g_ctx[((size_t)(b * SS + row) * HH + h) * EE + e] = acc[i][j] * inv;
        }
    }
}

// ---------------------------------------------------------------------------
extern "C" void kernel_launch(void* const* d_in, const int* in_sizes, int n_in,
                              void* d_out, int out_size)
{
    (void)in_sizes; (void)n_in; (void)out_size;
    const float* query = (const float*)d_in[0];
    const float* key   = (const float*)d_in[1];
    const float* value = (const float*)d_in[2];
    const float* Wq    = (const float*)d_in[3];
    const float* bq    = (const float*)d_in[4];
    const float* Wk    = (const float*)d_in[5];
    const float* bk    = (const float*)d_in[6];
    const float* Wv    = (const float*)d_in[7];
    const float* bv    = (const float*)d_in[8];
    const float* Wo    = (const float*)d_in[9];
    const float* bo    = (const float*)d_in[10];
    const float* sel   = (const float*)d_in[11];
    float* out = (float*)d_out;

    // allow >48KB dynamic shared for the attention kernel (idempotent)
    cudaFuncSetAttribute(attn_kernel, cudaFuncAttributeMaxDynamicSharedMemorySize,
                         ATTN_SMEM_FLOATS * (int)sizeof(float));

    dim3 gblk(256);
    dim3 ggrid(DD / 128, (BB * SS) / 128);  // 8 x 64

    proj_gemm<<<ggrid, gblk>>>(query, Wq, bq, 0);
    proj_gemm<<<ggrid, gblk>>>(key,   Wk, bk, 1);
    proj_gemm<<<ggrid, gblk>>>(value, Wv, bv, 2);

    attn_kernel<<<dim3(SS / 64, BB * HH), 256,
                  ATTN_SMEM_FLOATS * sizeof(float)>>>(sel);

    out_gemm<<<ggrid, gblk>>>(Wo, bo, out);
}

// round 3
// speedup vs baseline: 2.7445x; 2.7445x over previous
#include <cuda_runtime.h>
#include <math.h>
#include <stdint.h>

#define BB 4
#define SS 2048
#define DD 1024
#define HH 16
#define EE 64

// Scratch (device globals: allocation-free per harness rules)
__device__ float g_Q[BB*HH*SS*EE];
__device__ float g_K[BB*HH*SS*EE];
__device__ float g_V[BB*HH*SS*EE];
__device__ float g_ctx[BB*SS*HH*EE];

__device__ __forceinline__ uint32_t f2tf(float x) {
    uint32_t u; asm("cvt.rna.tf32.f32 %0, %1;" : "=r"(u) : "f"(x)); return u;
}

__device__ __forceinline__ void mma_tf32(float d[4], const uint32_t a[4],
                                         const uint32_t b[2], const float c[4]) {
    asm volatile("mma.sync.aligned.m16n8k8.row.col.f32.tf32.tf32.f32 "
        "{%0,%1,%2,%3}, {%4,%5,%6,%7}, {%8,%9}, {%10,%11,%12,%13};\n"
        : "=f"(d[0]), "=f"(d[1]), "=f"(d[2]), "=f"(d[3])
        : "r"(a[0]), "r"(a[1]), "r"(a[2]), "r"(a[3]),
          "r"(b[0]), "r"(b[1]),
          "f"(c[0]), "f"(c[1]), "f"(c[2]), "f"(c[3]));
}

// ---------------------------------------------------------------------------
// Projection GEMM (tf32 tensor cores):
//   out[b,h,s,e] = sum_d A[(b,s),d] * W[h,d,e] + bias[h,e]
// Tile 128x128xBK32, 256 thr = 8 warps (2m x 4n), warp tile 64x32.
// As layout [m][k] pad->36 (bank = 4*(lane/4)+lane%4 : conflict-free a-frags)
// Bs layout [k][n] pad->136 (bank = 8*(lane%4)+lane/4 : conflict-free b-frags)
// ---------------------------------------------------------------------------
__global__ __launch_bounds__(256, 2)
void proj_gemm_tc(const float* __restrict__ A, const float* __restrict__ W,
                  const float* __restrict__ bias, int which)
{
    __shared__ uint32_t As[128][36];
    __shared__ uint32_t Bs[32][136];

    float* outp = (which == 0) ? g_Q : (which == 1) ? g_K : g_V;

    int tid = threadIdx.x, lane = tid & 31, wid = tid >> 5;
    int g = lane >> 2, q4 = lane & 3;
    int wm = wid >> 2, wn = wid & 3;
    int m0 = blockIdx.y * 128, n0 = blockIdx.x * 128;

    float acc[4][4][4] = {};

    int aRow = tid >> 1, aCol = (tid & 1) * 16;
    int bRow = tid >> 3, bCol = (tid & 7) * 16;
    const float* Ap = A + (m0 + aRow) * DD + aCol;
    int bHead = (n0 + bCol) >> 6, bE = (n0 + bCol) & 63;
    const float* Wp = W + (size_t)bHead * DD * EE + bE;

    for (int k0 = 0; k0 < DD; k0 += 32) {
        float4 av[4], bv[4];
#pragma unroll
        for (int i = 0; i < 4; i++) av[i] = *(const float4*)(Ap + k0 + 4 * i);
#pragma unroll
        for (int i = 0; i < 4; i++) bv[i] = *(const float4*)(Wp + (size_t)(k0 + bRow) * EE + 4 * i);
        __syncthreads();
#pragma unroll
        for (int i = 0; i < 4; i++) {
            uint4 ua = {f2tf(av[i].x), f2tf(av[i].y), f2tf(av[i].z), f2tf(av[i].w)};
            *(uint4*)&As[aRow][aCol + 4 * i] = ua;
            uint4 ub = {f2tf(bv[i].x), f2tf(bv[i].y), f2tf(bv[i].z), f2tf(bv[i].w)};
            *(uint4*)&Bs[bRow][bCol + 4 * i] = ub;
        }
        __syncthreads();
#pragma unroll
        for (int ks = 0; ks < 4; ks++) {
            uint32_t a[4][4], b[4][2];
#pragma unroll
            for (int mt = 0; mt < 4; mt++) {
                int r = wm * 64 + mt * 16 + g, c = ks * 8 + q4;
                a[mt][0] = As[r][c];     a[mt][1] = As[r + 8][c];
                a[mt][2] = As[r][c + 4]; a[mt][3] = As[r + 8][c + 4];
            }
#pragma unroll
            for (int nt = 0; nt < 4; nt++) {
                int rr = ks * 8 + q4, cc = wn * 32 + nt * 8 + g;
                b[nt][0] = Bs[rr][cc]; b[nt][1] = Bs[rr + 4][cc];
            }
#pragma unroll
            for (int mt = 0; mt < 4; mt++)
#pragma unroll
                for (int nt = 0; nt < 4; nt++)
                    mma_tf32(acc[mt][nt], a[mt], b[nt], acc[mt][nt]);
        }
    }

#pragma unroll
    for (int mt = 0; mt < 4; mt++) {
#pragma unroll
        for (int rr = 0; rr < 2; rr++) {
            int m = m0 + wm * 64 + mt * 16 + g + rr * 8;
            int b_ = m >> 11, s = m & 2047;
#pragma unroll
            for (int nt = 0; nt < 4; nt++) {
                int n = n0 + wn * 32 + nt * 8 + q4 * 2;
                int h = n >> 6, e = n & 63;
                float2 o;
                o.x = acc[mt][nt][rr * 2 + 0] + bias[n];
                o.y = acc[mt][nt][rr * 2 + 1] + bias[n + 1];
                *(float2*)&outp[(((size_t)(b_ * HH + h) * SS) + s) * EE + e] = o;
            }
        }
    }
}

// ---------------------------------------------------------------------------
// Output GEMM (tf32): out[(b,s),n] = sum_k g_ctx[(b,s),k]*Wo[k,n] + bo[n]
// ---------------------------------------------------------------------------
__global__ __launch_bounds__(256, 2)
void out_gemm_tc(const float* __restrict__ Wo, const float* __restrict__ bo,
                 float* __restrict__ out)
{
    __shared__ uint32_t As[128][36];
    __shared__ uint32_t Bs[32][136];

    int tid = threadIdx.x, lane = tid & 31, wid = tid >> 5;
    int g = lane >> 2, q4 = lane & 3;
    int wm = wid >> 2, wn = wid & 3;
    int m0 = blockIdx.y * 128, n0 = blockIdx.x * 128;

    float acc[4][4][4] = {};

    int aRow = tid >> 1, aCol = (tid & 1) * 16;
    int bRow = tid >> 3, bCol = (tid & 7) * 16;
    const float* Ap = g_ctx + (size_t)(m0 + aRow) * DD + aCol;
    const float* Wp = Wo + n0 + bCol;

    for (int k0 = 0; k0 < DD; k0 += 32) {
        float4 av[4], bv[4];
#pragma unroll
        for (int i = 0; i < 4; i++) av[i] = *(const float4*)(Ap + k0 + 4 * i);
#pragma unroll
        for (int i = 0; i < 4; i++) bv[i] = *(const float4*)(Wp + (size_t)(k0 + bRow) * DD + 4 * i);
        __syncthreads();
#pragma unroll
        for (int i = 0; i < 4; i++) {
            uint4 ua = {f2tf(av[i].x), f2tf(av[i].y), f2tf(av[i].z), f2tf(av[i].w)};
            *(uint4*)&As[aRow][aCol + 4 * i] = ua;
            uint4 ub = {f2tf(bv[i].x), f2tf(bv[i].y), f2tf(bv[i].z), f2tf(bv[i].w)};
            *(uint4*)&Bs[bRow][bCol + 4 * i] = ub;
        }
        __syncthreads();
#pragma unroll
        for (int ks = 0; ks < 4; ks++) {
            uint32_t a[4][4], b[4][2];
#pragma unroll
            for (int mt = 0; mt < 4; mt++) {
                int r = wm * 64 + mt * 16 + g, c = ks * 8 + q4;
                a[mt][0] = As[r][c];     a[mt][1] = As[r + 8][c];
                a[mt][2] = As[r][c + 4]; a[mt][3] = As[r + 8][c + 4];
            }
#pragma unroll
            for (int nt = 0; nt < 4; nt++) {
                int rr = ks * 8 + q4, cc = wn * 32 + nt * 8 + g;
                b[nt][0] = Bs[rr][cc]; b[nt][1] = Bs[rr + 4][cc];
            }
#pragma unroll
            for (int mt = 0; mt < 4; mt++)
#pragma unroll
                for (int nt = 0; nt < 4; nt++)
                    mma_tf32(acc[mt][nt], a[mt], b[nt], acc[mt][nt]);
        }
    }

#pragma unroll
    for (int mt = 0; mt < 4; mt++) {
#pragma unroll
        for (int rr = 0; rr < 2; rr++) {
            int m = m0 + wm * 64 + mt * 16 + g + rr * 8;
#pragma unroll
            for (int nt = 0; nt < 4; nt++) {
                int n = n0 + wn * 32 + nt * 8 + q4 * 2;
                float2 o;
                o.x = acc[mt][nt][rr * 2 + 0] + bo[n];
                o.y = acc[mt][nt][rr * 2 + 1] + bo[n + 1];
                *(float2*)&out[(size_t)m * DD + n] = o;
            }
        }
    }
}

// ---------------------------------------------------------------------------
// Flash attention (tf32 tensor cores), per (b,h):
// Block = 128 q-rows, 8 warps; warp w owns rows [16w,16w+16) x ALL 64 cols
// -> softmax row reduction is intra-warp (shfl_xor 1,2 over the quad).
// K-tiles of 64. P round-trips through per-warp smem slice (syncwarp only).
// ---------------------------------------------------------------------------
#define ATTN_SMEM_BYTES ((128*68 + 64*68 + 64*72 + 128*68) * 4)

__global__ __launch_bounds__(256)
void attn_tc(const float* __restrict__ sel)
{
    extern __shared__ uint32_t smx[];
    uint32_t (*Qs)[68] = (uint32_t(*)[68])smx;                            // [128][68] A-layout
    uint32_t (*Ks)[68] = (uint32_t(*)[68])(smx + 128 * 68);               // [64][68]  [seq][e]
    uint32_t (*Vs)[72] = (uint32_t(*)[72])(smx + 128 * 68 + 64 * 68);     // [64][72]  [seq][e]
    uint32_t (*Ps)[68] = (uint32_t(*)[68])(smx + 128 * 68 + 64 * 68 + 64 * 72); // [128][68]

    int tid = threadIdx.x, lane = tid & 31, wid = tid >> 5;
    int g = lane >> 2, q4 = lane & 3;
    int bh = blockIdx.y, b = bh >> 4, h = bh & 15, qt = blockIdx.x;

    // head weight = softmax(sel)[h]
    float hm = -1e30f;
#pragma unroll
    for (int i = 0; i < HH; i++) hm = fmaxf(hm, sel[i]);
    float hsum = 0.f;
#pragma unroll
    for (int i = 0; i < HH; i++) hsum += __expf(sel[i] - hm);
    float hw = __expf(sel[h] - hm) / hsum;

    const float* Qg = g_Q + ((size_t)bh * SS + qt * 128) * EE;
    const float* Kg = g_K + (size_t)bh * SS * EE;
    const float* Vg = g_V + (size_t)bh * SS * EE;

    // load Q tile [128][64] -> tf32 smem
#pragma unroll
    for (int l = 0; l < 8; l++) {
        int idx = tid + l * 256;
        int r = idx >> 4, c = (idx & 15) * 4;
        float4 v = *(const float4*)(Qg + (size_t)r * EE + c);
        uint4 u = {f2tf(v.x), f2tf(v.y), f2tf(v.z), f2tf(v.w)};
        *(uint4*)&Qs[r][c] = u;
    }

    float o[8][4] = {};
    float m0r = -1e30f, m1r = -1e30f, l0r = 0.f, l1r = 0.f;
    int mrow = wid * 16;

    for (int kt = 0; kt < SS / 64; kt++) {
        __syncthreads();   // prior tile's Ks/Vs reads (and Ps reads) done
#pragma unroll
        for (int l = 0; l < 4; l++) {
            int idx = tid + l * 256;
            int r = idx >> 4, c = (idx & 15) * 4;
            float4 kv = *(const float4*)(Kg + (size_t)(kt * 64 + r) * EE + c);
            float4 vv = *(const float4*)(Vg + (size_t)(kt * 64 + r) * EE + c);
            uint4 ku = {f2tf(kv.x), f2tf(kv.y), f2tf(kv.z), f2tf(kv.w)};
            uint4 vu = {f2tf(vv.x), f2tf(vv.y), f2tf(vv.z), f2tf(vv.w)};
            *(uint4*)&Ks[r][c] = ku;
            *(uint4*)&Vs[r][c] = vu;
        }
        __syncthreads();

        // S = Q K^T (warp: 16 rows x 64 cols), k-dim = E = 64
        float s[8][4] = {};
#pragma unroll
        for (int ks = 0; ks < 8; ks++) {
            uint32_t a[4];
            int r = mrow + g, c = ks * 8 + q4;
            a[0] = Qs[r][c];     a[1] = Qs[r + 8][c];
            a[2] = Qs[r][c + 4]; a[3] = Qs[r + 8][c + 4];
#pragma unroll
            for (int nt = 0; nt < 8; nt++) {
                uint32_t bf[2];
                bf[0] = Ks[nt * 8 + g][ks * 8 + q4];
                bf[1] = Ks[nt * 8 + g][ks * 8 + q4 + 4];
                mma_tf32(s[nt], a, bf, s[nt]);
            }
        }

        // online softmax (rows g and g+8 of warp band; reduce over quad lanes)
        float mx0 = -1e30f, mx1 = -1e30f;
#pragma unroll
        for (int nt = 0; nt < 8; nt++) {
            s[nt][0] *= 0.125f; s[nt][1] *= 0.125f;
            s[nt][2] *= 0.125f; s[nt][3] *= 0.125f;
            mx0 = fmaxf(mx0, fmaxf(s[nt][0], s[nt][1]));
            mx1 = fmaxf(mx1, fmaxf(s[nt][2], s[nt][3]));
        }
        mx0 = fmaxf(mx0, __shfl_xor_sync(0xffffffffu, mx0, 1));
        mx0 = fmaxf(mx0, __shfl_xor_sync(0xffffffffu, mx0, 2));
        mx1 = fmaxf(mx1, __shfl_xor_sync(0xffffffffu, mx1, 1));
        mx1 = fmaxf(mx1, __shfl_xor_sync(0xffffffffu, mx1, 2));
        float nm0 = fmaxf(m0r, mx0), nm1 = fmaxf(m1r, mx1);
        float al0 = __expf(m0r - nm0), al1 = __expf(m1r - nm1);
        m0r = nm0; m1r = nm1;
        float sum0 = 0.f, sum1 = 0.f;
#pragma unroll
        for (int nt = 0; nt < 8; nt++) {
            s[nt][0] = __expf(s[nt][0] - nm0); s[nt][1] = __expf(s[nt][1] - nm0);
            s[nt][2] = __expf(s[nt][2] - nm1); s[nt][3] = __expf(s[nt][3] - nm1);
            sum0 += s[nt][0] + s[nt][1];
            sum1 += s[nt][2] + s[nt][3];
        }
        sum0 += __shfl_xor_sync(0xffffffffu, sum0, 1);
        sum0 += __shfl_xor_sync(0xffffffffu, sum0, 2);
        sum1 += __shfl_xor_sync(0xffffffffu, sum1, 1);
        sum1 += __shfl_xor_sync(0xffffffffu, sum1, 2);
        l0r = l0r * al0 + sum0;
        l1r = l1r * al1 + sum1;

        // rescale O accumulators, write P (tf32) to this warp's Ps slice
#pragma unroll
        for (int nt = 0; nt < 8; nt++) {
            o[nt][0] *= al0; o[nt][1] *= al0;
            o[nt][2] *= al1; o[nt][3] *= al1;
            uint2 p0 = {f2tf(s[nt][0]), f2tf(s[nt][1])};
            uint2 p1 = {f2tf(s[nt][2]), f2tf(s[nt][3])};
            *(uint2*)&Ps[mrow + g][nt * 8 + q4 * 2] = p0;
            *(uint2*)&Ps[mrow + g + 8][nt * 8 + q4 * 2] = p1;
        }
        __syncwarp();

        // O += P V   (k-dim = 64 seq cols)
#pragma unroll
        for (int ks = 0; ks < 8; ks++) {
            uint32_t a[4];
            int r = mrow + g, c = ks * 8 + q4;
            a[0] = Ps[r][c];     a[1] = Ps[r + 8][c];
            a[2] = Ps[r][c + 4]; a[3] = Ps[r + 8][c + 4];
#pragma unroll
            for (int nt = 0; nt < 8; nt++) {
                uint32_t bf[2];
                bf[0] = Vs[ks * 8 + q4][nt * 8 + g];
                bf[1] = Vs[ks * 8 + q4 + 4][nt * 8 + g];
                mma_tf32(o[nt], a, bf, o[nt]);
            }
        }
    }

    // epilogue: normalize, gate, write ctx [B,S,H*E]
    float inv0 = hw / l0r, inv1 = hw / l1r;
#pragma unroll
    for (int nt = 0; nt < 8; nt++) {
        int e = nt * 8 + q4 * 2;
        int r0 = qt * 128 + mrow + g, r1 = r0 + 8;
        float2 x0 = {o[nt][0] * inv0, o[nt][1] * inv0};
        float2 x1 = {o[nt][2] * inv1, o[nt][3] * inv1};
        *(float2*)&g_ctx[((size_t)(b * SS + r0) * HH + h) * EE + e] = x0;
        *(float2*)&g_ctx[((size_t)(b * SS + r1) * HH + h) * EE + e] = x1;
    }
}

// ---------------------------------------------------------------------------
extern "C" void kernel_launch(void* const* d_in, const int* in_sizes, int n_in,
                              void* d_out, int out_size)
{
    (void)in_sizes; (void)n_in; (void)out_size;
    const float* query = (const float*)d_in[0];
    const float* key   = (const float*)d_in[1];
    const float* value = (const float*)d_in[2];
    const float* Wq    = (const float*)d_in[3];
    const float* bq    = (const float*)d_in[4];
    const float* Wk    = (const float*)d_in[5];
    const float* bk    = (const float*)d_in[6];
    const float* Wv    = (const float*)d_in[7];
    const float* bv    = (const float*)d_in[8];
    const float* Wo    = (const float*)d_in[9];
    const float* bo    = (const float*)d_in[10];
    const float* sel   = (const float*)d_in[11];
    float* out = (float*)d_out;

    cudaFuncSetAttribute(attn_tc, cudaFuncAttributeMaxDynamicSharedMemorySize,
                         ATTN_SMEM_BYTES);

    dim3 gblk(256);
    dim3 ggrid(DD / 128, (BB * SS) / 128);  // 8 x 64

    proj_gemm_tc<<<ggrid, gblk>>>(query, Wq, bq, 0);
    proj_gemm_tc<<<ggrid, gblk>>>(key,   Wk, bk, 1);
    proj_gemm_tc<<<ggrid, gblk>>>(value, Wv, bv, 2);

    attn_tc<<<dim3(SS / 128, BB * HH), 256, ATTN_SMEM_BYTES>>>(sel);

    out_gemm_tc<<<ggrid, gblk>>>(Wo, bo, out);
}

// round 4
// speedup vs baseline: 2.7514x; 1.0025x over previous
#include <cuda_runtime.h>
#include <math.h>
#include <stdint.h>

#define BB 4
#define SS 2048
#define DD 1024
#define HH 16
#define EE 64

// Scratch (device globals: allocation-free per harness rules)
__device__ float g_Q[BB*HH*SS*EE];
__device__ float g_K[BB*HH*SS*EE];
__device__ float g_V[BB*HH*SS*EE];
__device__ float g_ctx[BB*SS*HH*EE];

__device__ __forceinline__ uint32_t f2tf(float x) {
    uint32_t u; asm("cvt.rna.tf32.f32 %0, %1;" : "=r"(u) : "f"(x)); return u;
}

__device__ __forceinline__ void mma_tf32(float d[4], const uint32_t a[4],
                                         const uint32_t b[2], const float c[4]) {
    asm volatile("mma.sync.aligned.m16n8k8.row.col.f32.tf32.tf32.f32 "
        "{%0,%1,%2,%3}, {%4,%5,%6,%7}, {%8,%9}, {%10,%11,%12,%13};\n"
        : "=f"(d[0]), "=f"(d[1]), "=f"(d[2]), "=f"(d[3])
        : "r"(a[0]), "r"(a[1]), "r"(a[2]), "r"(a[3]),
          "r"(b[0]), "r"(b[1]),
          "f"(c[0]), "f"(c[1]), "f"(c[2]), "f"(c[3]));
}

// ---------------------------------------------------------------------------
// Projection GEMM (tf32 tensor cores):
//   out[b,h,s,e] = sum_d A[(b,s),d] * W[h,d,e] + bias[h,e]
// Tile 128x128xBK32, 256 thr = 8 warps (2m x 4n), warp tile 64x32.
// As layout [m][k] pad->36 (bank = 4*(lane/4)+lane%4 : conflict-free a-frags)
// Bs layout [k][n] pad->136 (bank = 8*(lane%4)+lane/4 : conflict-free b-frags)
// ---------------------------------------------------------------------------
__global__ __launch_bounds__(256, 2)
void proj_gemm_tc(const float* __restrict__ A, const float* __restrict__ W,
                  const float* __restrict__ bias, int which)
{
    __shared__ uint32_t As[128][36];
    __shared__ uint32_t Bs[32][136];

    float* outp = (which == 0) ? g_Q : (which == 1) ? g_K : g_V;

    int tid = threadIdx.x, lane = tid & 31, wid = tid >> 5;
    int g = lane >> 2, q4 = lane & 3;
    int wm = wid >> 2, wn = wid & 3;
    int m0 = blockIdx.y * 128, n0 = blockIdx.x * 128;

    float acc[4][4][4] = {};

    int aRow = tid >> 1, aCol = (tid & 1) * 16;
    int bRow = tid >> 3, bCol = (tid & 7) * 16;
    const float* Ap = A + (m0 + aRow) * DD + aCol;
    int bHead = (n0 + bCol) >> 6, bE = (n0 + bCol) & 63;
    const float* Wp = W + (size_t)bHead * DD * EE + bE;

    for (int k0 = 0; k0 < DD; k0 += 32) {
        float4 av[4], bv[4];
#pragma unroll
        for (int i = 0; i < 4; i++) av[i] = *(const float4*)(Ap + k0 + 4 * i);
#pragma unroll
        for (int i = 0; i < 4; i++) bv[i] = *(const float4*)(Wp + (size_t)(k0 + bRow) * EE + 4 * i);
        __syncthreads();
#pragma unroll
        for (int i = 0; i < 4; i++) {
            uint4 ua = {f2tf(av[i].x), f2tf(av[i].y), f2tf(av[i].z), f2tf(av[i].w)};
            *(uint4*)&As[aRow][aCol + 4 * i] = ua;
            uint4 ub = {f2tf(bv[i].x), f2tf(bv[i].y), f2tf(bv[i].z), f2tf(bv[i].w)};
            *(uint4*)&Bs[bRow][bCol + 4 * i] = ub;
        }
        __syncthreads();
#pragma unroll
        for (int ks = 0; ks < 4; ks++) {
            uint32_t a[4][4], b[4][2];
#pragma unroll
            for (int mt = 0; mt < 4; mt++) {
                int r = wm * 64 + mt * 16 + g, c = ks * 8 + q4;
                a[mt][0] = As[r][c];     a[mt][1] = As[r + 8][c];
                a[mt][2] = As[r][c + 4]; a[mt][3] = As[r + 8][c + 4];
            }
#pragma unroll
            for (int nt = 0; nt < 4; nt++) {
                int rr = ks * 8 + q4, cc = wn * 32 + nt * 8 + g;
                b[nt][0] = Bs[rr][cc]; b[nt][1] = Bs[rr + 4][cc];
            }
#pragma unroll
            for (int mt = 0; mt < 4; mt++)
#pragma unroll
                for (int nt = 0; nt < 4; nt++)
                    mma_tf32(acc[mt][nt], a[mt], b[nt], acc[mt][nt]);
        }
    }

#pragma unroll
    for (int mt = 0; mt < 4; mt++) {
#pragma unroll
        for (int rr = 0; rr < 2; rr++) {
            int m = m0 + wm * 64 + mt * 16 + g + rr * 8;
            int b_ = m >> 11, s = m & 2047;
#pragma unroll
            for (int nt = 0; nt < 4; nt++) {
                int n = n0 + wn * 32 + nt * 8 + q4 * 2;
                int h = n >> 6, e = n & 63;
                float2 o;
                o.x = acc[mt][nt][rr * 2 + 0] + bias[n];
                o.y = acc[mt][nt][rr * 2 + 1] + bias[n + 1];
                *(float2*)&outp[(((size_t)(b_ * HH + h) * SS) + s) * EE + e] = o;
            }
        }
    }
}

// ---------------------------------------------------------------------------
// Output GEMM (tf32): out[(b,s),n] = sum_k g_ctx[(b,s),k]*Wo[k,n] + bo[n]
// ---------------------------------------------------------------------------
__global__ __launch_bounds__(256, 2)
void out_gemm_tc(const float* __restrict__ Wo, const float* __restrict__ bo,
                 float* __restrict__ out)
{
    __shared__ uint32_t As[128][36];
    __shared__ uint32_t Bs[32][136];

    int tid = threadIdx.x, lane = tid & 31, wid = tid >> 5;
    int g = lane >> 2, q4 = lane & 3;
    int wm = wid >> 2, wn = wid & 3;
    int m0 = blockIdx.y * 128, n0 = blockIdx.x * 128;

    float acc[4][4][4] = {};

    int aRow = tid >> 1, aCol = (tid & 1) * 16;
    int bRow = tid >> 3, bCol = (tid & 7) * 16;
    const float* Ap = g_ctx + (size_t)(m0 + aRow) * DD + aCol;
    const float* Wp = Wo + n0 + bCol;

    for (int k0 = 0; k0 < DD; k0 += 32) {
        float4 av[4], bv[4];
#pragma unroll
        for (int i = 0; i < 4; i++) av[i] = *(const float4*)(Ap + k0 + 4 * i);
#pragma unroll
        for (int i = 0; i < 4; i++) bv[i] = *(const float4*)(Wp + (size_t)(k0 + bRow) * DD + 4 * i);
        __syncthreads();
#pragma unroll
        for (int i = 0; i < 4; i++) {
            uint4 ua = {f2tf(av[i].x), f2tf(av[i].y), f2tf(av[i].z), f2tf(av[i].w)};
            *(uint4*)&As[aRow][aCol + 4 * i] = ua;
            uint4 ub = {f2tf(bv[i].x), f2tf(bv[i].y), f2tf(bv[i].z), f2tf(bv[i].w)};
            *(uint4*)&Bs[bRow][bCol + 4 * i] = ub;
        }
        __syncthreads();
#pragma unroll
        for (int ks = 0; ks < 4; ks++) {
            uint32_t a[4][4], b[4][2];
#pragma unroll
            for (int mt = 0; mt < 4; mt++) {
                int r = wm * 64 + mt * 16 + g, c = ks * 8 + q4;
                a[mt][0] = As[r][c];     a[mt][1] = As[r + 8][c];
                a[mt][2] = As[r][c + 4]; a[mt][3] = As[r + 8][c + 4];
            }
#pragma unroll
            for (int nt = 0; nt < 4; nt++) {
                int rr = ks * 8 + q4, cc = wn * 32 + nt * 8 + g;
                b[nt][0] = Bs[rr][cc]; b[nt][1] = Bs[rr + 4][cc];
            }
#pragma unroll
            for (int mt = 0; mt < 4; mt++)
#pragma unroll
                for (int nt = 0; nt < 4; nt++)
                    mma_tf32(acc[mt][nt], a[mt], b[nt], acc[mt][nt]);
        }
    }

#pragma unroll
    for (int mt = 0; mt < 4; mt++) {
#pragma unroll
        for (int rr = 0; rr < 2; rr++) {
            int m = m0 + wm * 64 + mt * 16 + g + rr * 8;
#pragma unroll
            for (int nt = 0; nt < 4; nt++) {
                int n = n0 + wn * 32 + nt * 8 + q4 * 2;
                float2 o;
                o.x = acc[mt][nt][rr * 2 + 0] + bo[n];
                o.y = acc[mt][nt][rr * 2 + 1] + bo[n + 1];
                *(float2*)&out[(size_t)m * DD + n] = o;
            }
        }
    }
}

// ---------------------------------------------------------------------------
// Flash attention (tf32 tensor cores), per (b,h):
// Block = 128 q-rows, 8 warps; warp w owns rows [16w,16w+16) x ALL 64 cols
// -> softmax row reduction is intra-warp (shfl_xor 1,2 over the quad).
// K-tiles of 64. P round-trips through per-warp smem slice (syncwarp only).
// ---------------------------------------------------------------------------
#define ATTN_SMEM_BYTES ((128*68 + 64*68 + 64*72 + 128*68) * 4)

__global__ __launch_bounds__(256)
void attn_tc(const float* __restrict__ sel)
{
    extern __shared__ uint32_t smx[];
    uint32_t (*Qs)[68] = (uint32_t(*)[68])smx;                            // [128][68] A-layout
    uint32_t (*Ks)[68] = (uint32_t(*)[68])(smx + 128 * 68);               // [64][68]  [seq][e]
    uint32_t (*Vs)[72] = (uint32_t(*)[72])(smx + 128 * 68 + 64 * 68);     // [64][72]  [seq][e]
    uint32_t (*Ps)[68] = (uint32_t(*)[68])(smx + 128 * 68 + 64 * 68 + 64 * 72); // [128][68]

    int tid = threadIdx.x, lane = tid & 31, wid = tid >> 5;
    int g = lane >> 2, q4 = lane & 3;
    int bh = blockIdx.y, b = bh >> 4, h = bh & 15, qt = blockIdx.x;

    // head weight = softmax(sel)[h]
    float hm = -1e30f;
#pragma unroll
    for (int i = 0; i < HH; i++) hm = fmaxf(hm, sel[i]);
    float hsum = 0.f;
#pragma unroll
    for (int i = 0; i < HH; i++) hsum += __expf(sel[i] - hm);
    float hw = __expf(sel[h] - hm) / hsum;

    const float* Qg = g_Q + ((size_t)bh * SS + qt * 128) * EE;
    const float* Kg = g_K + (size_t)bh * SS * EE;
    const float* Vg = g_V + (size_t)bh * SS * EE;

    // load Q tile [128][64] -> tf32 smem
#pragma unroll
    for (int l = 0; l < 8; l++) {
        int idx = tid + l * 256;
        int r = idx >> 4, c = (idx & 15) * 4;
        float4 v = *(const float4*)(Qg + (size_t)r * EE + c);
        uint4 u = {f2tf(v.x), f2tf(v.y), f2tf(v.z), f2tf(v.w)};
        *(uint4*)&Qs[r][c] = u;
    }

    float o[8][4] = {};
    float m0r = -1e30f, m1r = -1e30f, l0r = 0.f, l1r = 0.f;
    int mrow = wid * 16;

    for (int kt = 0; kt < SS / 64; kt++) {
        __syncthreads();   // prior tile's Ks/Vs reads (and Ps reads) done
#pragma unroll
        for (int l = 0; l < 4; l++) {
            int idx = tid + l * 256;
            int r = idx >> 4, c = (idx & 15) * 4;
            float4 kv = *(const float4*)(Kg + (size_t)(kt * 64 + r) * EE + c);
            float4 vv = *(const float4*)(Vg + (size_t)(kt * 64 + r) * EE + c);
            uint4 ku = {f2tf(kv.x), f2tf(kv.y), f2tf(kv.z), f2tf(kv.w)};
            uint4 vu = {f2tf(vv.x), f2tf(vv.y), f2tf(vv.z), f2tf(vv.w)};
            *(uint4*)&Ks[r][c] = ku;
            *(uint4*)&Vs[r][c] = vu;
        }
        __syncthreads();

        // S = Q K^T (warp: 16 rows x 64 cols), k-dim = E = 64
        float s[8][4] = {};
#pragma unroll
        for (int ks = 0; ks < 8; ks++) {
            uint32_t a[4];
            int r = mrow + g, c = ks * 8 + q4;
            a[0] = Qs[r][c];     a[1] = Qs[r + 8][c];
            a[2] = Qs[r][c + 4]; a[3] = Qs[r + 8][c + 4];
#pragma unroll
            for (int nt = 0; nt < 8; nt++) {
                uint32_t bf[2];
                bf[0] = Ks[nt * 8 + g][ks * 8 + q4];
                bf[1] = Ks[nt * 8 + g][ks * 8 + q4 + 4];
                mma_tf32(s[nt], a, bf, s[nt]);
            }
        }

        // online softmax (rows g and g+8 of warp band; reduce over quad lanes)
        float mx0 = -1e30f, mx1 = -1e30f;
#pragma unroll
        for (int nt = 0; nt < 8; nt++) {
            s[nt][0] *= 0.125f; s[nt][1] *= 0.125f;
            s[nt][2] *= 0.125f; s[nt][3] *= 0.125f;
            mx0 = fmaxf(mx0, fmaxf(s[nt][0], s[nt][1]));
            mx1 = fmaxf(mx1, fmaxf(s[nt][2], s[nt][3]));
        }
        mx0 = fmaxf(mx0, __shfl_xor_sync(0xffffffffu, mx0, 1));
        mx0 = fmaxf(mx0, __shfl_xor_sync(0xffffffffu, mx0, 2));
        mx1 = fmaxf(mx1, __shfl_xor_sync(0xffffffffu, mx1, 1));
        mx1 = fmaxf(mx1, __shfl_xor_sync(0xffffffffu, mx1, 2));
        float nm0 = fmaxf(m0r, mx0), nm1 = fmaxf(m1r, mx1);
        float al0 = __expf(m0r - nm0), al1 = __expf(m1r - nm1);
        m0r = nm0; m1r = nm1;
        float sum0 = 0.f, sum1 = 0.f;
#pragma unroll
        for (int nt = 0; nt < 8; nt++) {
            s[nt][0] = __expf(s[nt][0] - nm0); s[nt][1] = __expf(s[nt][1] - nm0);
            s[nt][2] = __expf(s[nt][2] - nm1); s[nt][3] = __expf(s[nt][3] - nm1);
            sum0 += s[nt][0] + s[nt][1];
            sum1 += s[nt][2] + s[nt][3];
        }
        sum0 += __shfl_xor_sync(0xffffffffu, sum0, 1);
        sum0 += __shfl_xor_sync(0xffffffffu, sum0, 2);
        sum1 += __shfl_xor_sync(0xffffffffu, sum1, 1);
        sum1 += __shfl_xor_sync(0xffffffffu, sum1, 2);
        l0r = l0r * al0 + sum0;
        l1r = l1r * al1 + sum1;

        // rescale O accumulators, write P (tf32) to this warp's Ps slice
#pragma unroll
        for (int nt = 0; nt < 8; nt++) {
            o[nt][0] *= al0; o[nt][1] *= al0;
            o[nt][2] *= al1; o[nt][3] *= al1;
            uint2 p0 = {f2tf(s[nt][0]), f2tf(s[nt][1])};
            uint2 p1 = {f2tf(s[nt][2]), f2tf(s[nt][3])};
            *(uint2*)&Ps[mrow + g][nt * 8 + q4 * 2] = p0;
            *(uint2*)&Ps[mrow + g + 8][nt * 8 + q4 * 2] = p1;
        }
        __syncwarp();

        // O += P V   (k-dim = 64 seq cols)
#pragma unroll
        for (int ks = 0; ks < 8; ks++) {
            uint32_t a[4];
            int r = mrow + g, c = ks * 8 + q4;
            a[0] = Ps[r][c];     a[1] = Ps[r + 8][c];
            a[2] = Ps[r][c + 4]; a[3] = Ps[r + 8][c + 4];
#pragma unroll
            for (int nt = 0; nt < 8; nt++) {
                uint32_t bf[2];
                bf[0] = Vs[ks * 8 + q4][nt * 8 + g];
                bf[1] = Vs[ks * 8 + q4 + 4][nt * 8 + g];
                mma_tf32(o[nt], a, bf, o[nt]);
            }
        }
    }

    // epilogue: normalize, gate, write ctx [B,S,H*E]
    float inv0 = hw / l0r, inv1 = hw / l1r;
#pragma unroll
    for (int nt = 0; nt < 8; nt++) {
        int e = nt * 8 + q4 * 2;
        int r0 = qt * 128 + mrow + g, r1 = r0 + 8;
        float2 x0 = {o[nt][0] * inv0, o[nt][1] * inv0};
        float2 x1 = {o[nt][2] * inv1, o[nt][3] * inv1};
        *(float2*)&g_ctx[((size_t)(b * SS + r0) * HH + h) * EE + e] = x0;
        *(float2*)&g_ctx[((size_t)(b * SS + r1) * HH + h) * EE + e] = x1;
    }
}

// ---------------------------------------------------------------------------
extern "C" void kernel_launch(void* const* d_in, const int* in_sizes, int n_in,
                              void* d_out, int out_size)
{
    (void)in_sizes; (void)n_in; (void)out_size;
    const float* query = (const float*)d_in[0];
    const float* key   = (const float*)d_in[1];
    const float* value = (const float*)d_in[2];
    const float* Wq    = (const float*)d_in[3];
    const float* bq    = (const float*)d_in[4];
    const float* Wk    = (const float*)d_in[5];
    const float* bk    = (const float*)d_in[6];
    const float* Wv    = (const float*)d_in[7];
    const float* bv    = (const float*)d_in[8];
    const float* Wo    = (const float*)d_in[9];
    const float* bo    = (const float*)d_in[10];
    const float* sel   = (const float*)d_in[11];
    float* out = (float*)d_out;

    cudaFuncSetAttribute(attn_tc, cudaFuncAttributeMaxDynamicSharedMemorySize,
                         ATTN_SMEM_BYTES);

    dim3 gblk(256);
    dim3 ggrid(DD / 128, (BB * SS) / 128);  // 8 x 64

    proj_gemm_tc<<<ggrid, gblk>>>(query, Wq, bq, 0);
    proj_gemm_tc<<<ggrid, gblk>>>(key,   Wk, bk, 1);
    proj_gemm_tc<<<ggrid, gblk>>>(value, Wv, bv, 2);

    attn_tc<<<dim3(SS / 128, BB * HH), 256, ATTN_SMEM_BYTES>>>(sel);

    out_gemm_tc<<<ggrid, gblk>>>(Wo, bo, out);
}

// round 5
// speedup vs baseline: 5.6419x; 2.0506x over previous
#include <cuda_runtime.h>
#include <cuda_fp16.h>
#include <math.h>
#include <stdint.h>

#define BB 4
#define SS 2048
#define DD 1024
#define HH 16
#define EE 64

// fp16 scratch (device globals: allocation-free per harness rules)
__device__ __half g_Q[BB*HH*SS*EE];
__device__ __half g_K[BB*HH*SS*EE];
__device__ __half g_V[BB*HH*SS*EE];
__device__ __half g_ctx[BB*SS*HH*EE];

// ---------------------------------------------------------------------------
// helpers
// ---------------------------------------------------------------------------
__device__ __forceinline__ void mma_f16(float d[4], const uint32_t a[4],
                                        const uint32_t b[2]) {
    asm volatile("mma.sync.aligned.m16n8k16.row.col.f32.f16.f16.f32 "
        "{%0,%1,%2,%3}, {%4,%5,%6,%7}, {%8,%9}, {%0,%1,%2,%3};"
        : "+f"(d[0]), "+f"(d[1]), "+f"(d[2]), "+f"(d[3])
        : "r"(a[0]), "r"(a[1]), "r"(a[2]), "r"(a[3]), "r"(b[0]), "r"(b[1]));
}

__device__ __forceinline__ void ldsm_x4(uint32_t r[4], uint32_t addr) {
    asm volatile("ldmatrix.sync.aligned.m8n8.x4.shared.b16 {%0,%1,%2,%3}, [%4];"
        : "=r"(r[0]), "=r"(r[1]), "=r"(r[2]), "=r"(r[3]) : "r"(addr));
}

__device__ __forceinline__ void ldsm_x4_t(uint32_t r[4], uint32_t addr) {
    asm volatile("ldmatrix.sync.aligned.m8n8.x4.trans.shared.b16 {%0,%1,%2,%3}, [%4];"
        : "=r"(r[0]), "=r"(r[1]), "=r"(r[2]), "=r"(r[3]) : "r"(addr));
}

__device__ __forceinline__ uint4 pack8(float4 a, float4 b) {
    __half2 h0 = __floats2half2_rn(a.x, a.y);
    __half2 h1 = __floats2half2_rn(a.z, a.w);
    __half2 h2 = __floats2half2_rn(b.x, b.y);
    __half2 h3 = __floats2half2_rn(b.z, b.w);
    uint4 u;
    u.x = *reinterpret_cast<uint32_t*>(&h0);
    u.y = *reinterpret_cast<uint32_t*>(&h1);
    u.z = *reinterpret_cast<uint32_t*>(&h2);
    u.w = *reinterpret_cast<uint32_t*>(&h3);
    return u;
}

// ---------------------------------------------------------------------------
// Projection GEMM (fp16 mma m16n8k16 + ldmatrix):
//   out[b,h,s,e] = (sum_d A[(b,s),d] * W[h,d,e] + bias[h,e]) * oscale  (half)
// Block tile 128x128xBK32, 8 warps (2m x 4n), warp tile 64x32.
// sA: [128][pad40 halves] rows of 80B (conflict-free ldmatrix: banks 20r+4c)
// sB: [32][pad136 halves] rows of 272B ([k][n], trans ldmatrix)
// ---------------------------------------------------------------------------
__global__ __launch_bounds__(256, 2)
void proj_gemm_h(const float* __restrict__ A, const float* __restrict__ W,
                 const float* __restrict__ bias, int which, float oscale)
{
    __shared__ alignas(16) char sA[128 * 80];
    __shared__ alignas(16) char sB[32 * 272];

    __half* outp = (which == 0) ? g_Q : (which == 1) ? g_K : g_V;

    int tid = threadIdx.x, lane = tid & 31, wid = tid >> 5;
    int g = lane >> 2, q4 = lane & 3;
    int wm = wid >> 2, wn = wid & 3;
    int m0 = blockIdx.y * 128, n0 = blockIdx.x * 128;

    uint32_t sA32 = (uint32_t)__cvta_generic_to_shared(sA);
    uint32_t sB32 = (uint32_t)__cvta_generic_to_shared(sB);

    float acc[4][4][4] = {};

    // loader indices (2 chunks each for A and B per iter)
    int acid0 = tid, acid1 = tid + 256;         // A chunks: r=cid>>2, kc=cid&3
    int ar0 = acid0 >> 2, akc0 = acid0 & 3;
    int ar1 = acid1 >> 2, akc1 = acid1 & 3;
    int bk0 = acid0 >> 4, bnc0 = acid0 & 15;    // B chunks: k=cid>>4, nc=cid&15
    int bk1 = acid1 >> 4, bnc1 = acid1 & 15;
    int bn0 = n0 + bnc0 * 8, bn1 = n0 + bnc1 * 8;
    const float* Wp0 = W + ((size_t)(bn0 >> 6) * DD) * EE + (bn0 & 63);
    const float* Wp1 = W + ((size_t)(bn1 >> 6) * DD) * EE + (bn1 & 63);

    // precomputed fragment addresses
    uint32_t aAddr[4], bAddr[2];
#pragma unroll
    for (int mt = 0; mt < 4; mt++) {
        int row = wm * 64 + mt * 16 + (lane & 15);
        aAddr[mt] = sA32 + row * 80 + (lane >> 4) * 16;   // + ks*32
    }
#pragma unroll
    for (int nt = 0; nt < 2; nt++) {
        int krow = lane & 15;
        bAddr[nt] = sB32 + krow * 272 + (wn * 4 + nt * 2 + (lane >> 4)) * 16; // + ks*16*272
    }

    for (int k0 = 0; k0 < DD; k0 += 32) {
        float4 af[2][2], bf[2][2];
        const float4* p;
        p = (const float4*)(A + (size_t)(m0 + ar0) * DD + k0 + akc0 * 8);
        af[0][0] = p[0]; af[0][1] = p[1];
        p = (const float4*)(A + (size_t)(m0 + ar1) * DD + k0 + akc1 * 8);
        af[1][0] = p[0]; af[1][1] = p[1];
        p = (const float4*)(Wp0 + (size_t)(k0 + bk0) * EE);
        bf[0][0] = p[0]; bf[0][1] = p[1];
        p = (const float4*)(Wp1 + (size_t)(k0 + bk1) * EE);
        bf[1][0] = p[0]; bf[1][1] = p[1];

        __syncthreads();
        *(uint4*)(sA + ar0 * 80 + akc0 * 16) = pack8(af[0][0], af[0][1]);
        *(uint4*)(sA + ar1 * 80 + akc1 * 16) = pack8(af[1][0], af[1][1]);
        *(uint4*)(sB + bk0 * 272 + bnc0 * 16) = pack8(bf[0][0], bf[0][1]);
        *(uint4*)(sB + bk1 * 272 + bnc1 * 16) = pack8(bf[1][0], bf[1][1]);
        __syncthreads();

#pragma unroll
        for (int ks = 0; ks < 2; ks++) {
            uint32_t a[4][4], b[2][4];
#pragma unroll
            for (int mt = 0; mt < 4; mt++) ldsm_x4(a[mt], aAddr[mt] + ks * 32);
#pragma unroll
            for (int nt = 0; nt < 2; nt++) ldsm_x4_t(b[nt], bAddr[nt] + ks * 16 * 272);
#pragma unroll
            for (int mt = 0; mt < 4; mt++)
#pragma unroll
                for (int nt = 0; nt < 2; nt++) {
                    mma_f16(acc[mt][nt * 2 + 0], a[mt], &b[nt][0]);
                    mma_f16(acc[mt][nt * 2 + 1], a[mt], &b[nt][2]);
                }
        }
    }

#pragma unroll
    for (int mt = 0; mt < 4; mt++) {
#pragma unroll
        for (int rr = 0; rr < 2; rr++) {
            int m = m0 + wm * 64 + mt * 16 + g + rr * 8;
            int b_ = m >> 11, s = m & 2047;
#pragma unroll
            for (int nn = 0; nn < 4; nn++) {
                int n = n0 + wn * 32 + nn * 8 + q4 * 2;
                int h = n >> 6, e = n & 63;
                float x = (acc[mt][nn][rr * 2 + 0] + bias[n]) * oscale;
                float y = (acc[mt][nn][rr * 2 + 1] + bias[n + 1]) * oscale;
                __half2 hv = __floats2half2_rn(x, y);
                *(__half2*)&outp[(((size_t)(b_ * HH + h)) * SS + s) * EE + e] = hv;
            }
        }
    }
}

// ---------------------------------------------------------------------------
// Output GEMM (fp16): out[(b,s),n] = sum_k g_ctx[(b,s),k]*Wo[k,n] + bo[n]
// A is already half; B converted fp32->half.
// ---------------------------------------------------------------------------
__global__ __launch_bounds__(256, 2)
void out_gemm_h(const float* __restrict__ Wo, const float* __restrict__ bo,
                float* __restrict__ out)
{
    __shared__ alignas(16) char sA[128 * 80];
    __shared__ alignas(16) char sB[32 * 272];

    int tid = threadIdx.x, lane = tid & 31, wid = tid >> 5;
    int g = lane >> 2, q4 = lane & 3;
    int wm = wid >> 2, wn = wid & 3;
    int m0 = blockIdx.y * 128, n0 = blockIdx.x * 128;

    uint32_t sA32 = (uint32_t)__cvta_generic_to_shared(sA);
    uint32_t sB32 = (uint32_t)__cvta_generic_to_shared(sB);

    float acc[4][4][4] = {};

    int acid0 = tid, acid1 = tid + 256;
    int ar0 = acid0 >> 2, akc0 = acid0 & 3;
    int ar1 = acid1 >> 2, akc1 = acid1 & 3;
    int bk0 = acid0 >> 4, bnc0 = acid0 & 15;
    int bk1 = acid1 >> 4, bnc1 = acid1 & 15;

    uint32_t aAddr[4], bAddr[2];
#pragma unroll
    for (int mt = 0; mt < 4; mt++) {
        int row = wm * 64 + mt * 16 + (lane & 15);
        aAddr[mt] = sA32 + row * 80 + (lane >> 4) * 16;
    }
#pragma unroll
    for (int nt = 0; nt < 2; nt++) {
        int krow = lane & 15;
        bAddr[nt] = sB32 + krow * 272 + (wn * 4 + nt * 2 + (lane >> 4)) * 16;
    }

    for (int k0 = 0; k0 < DD; k0 += 32) {
        uint4 ah0 = *(const uint4*)(g_ctx + (size_t)(m0 + ar0) * DD + k0 + akc0 * 8);
        uint4 ah1 = *(const uint4*)(g_ctx + (size_t)(m0 + ar1) * DD + k0 + akc1 * 8);
        const float4* p;
        float4 bf0a, bf0b, bf1a, bf1b;
        p = (const float4*)(Wo + (size_t)(k0 + bk0) * DD + n0 + bnc0 * 8);
        bf0a = p[0]; bf0b = p[1];
        p = (const float4*)(Wo + (size_t)(k0 + bk1) * DD + n0 + bnc1 * 8);
        bf1a = p[0]; bf1b = p[1];

        __syncthreads();
        *(uint4*)(sA + ar0 * 80 + akc0 * 16) = ah0;
        *(uint4*)(sA + ar1 * 80 + akc1 * 16) = ah1;
        *(uint4*)(sB + bk0 * 272 + bnc0 * 16) = pack8(bf0a, bf0b);
        *(uint4*)(sB + bk1 * 272 + bnc1 * 16) = pack8(bf1a, bf1b);
        __syncthreads();

#pragma unroll
        for (int ks = 0; ks < 2; ks++) {
            uint32_t a[4][4], b[2][4];
#pragma unroll
            for (int mt = 0; mt < 4; mt++) ldsm_x4(a[mt], aAddr[mt] + ks * 32);
#pragma unroll
            for (int nt = 0; nt < 2; nt++) ldsm_x4_t(b[nt], bAddr[nt] + ks * 16 * 272);
#pragma unroll
            for (int mt = 0; mt < 4; mt++)
#pragma unroll
                for (int nt = 0; nt < 2; nt++) {
                    mma_f16(acc[mt][nt * 2 + 0], a[mt], &b[nt][0]);
                    mma_f16(acc[mt][nt * 2 + 1], a[mt], &b[nt][2]);
                }
        }
    }

#pragma unroll
    for (int mt = 0; mt < 4; mt++) {
#pragma unroll
        for (int rr = 0; rr < 2; rr++) {
            int m = m0 + wm * 64 + mt * 16 + g + rr * 8;
#pragma unroll
            for (int nn = 0; nn < 4; nn++) {
                int n = n0 + wn * 32 + nn * 8 + q4 * 2;
                float2 o;
                o.x = acc[mt][nn][rr * 2 + 0] + bo[n];
                o.y = acc[mt][nn][rr * 2 + 1] + bo[n + 1];
                *(float2*)&out[(size_t)m * DD + n] = o;
            }
        }
    }
}

// ---------------------------------------------------------------------------
// Flash attention (fp16 mma + ldmatrix), per (b,h):
// Block = 128 q-rows, 8 warps; warp owns 16 rows x all 64 key-cols.
// Tiles in smem: rows padded to 144B (72 halves) -> conflict-free ldmatrix.
// Q pre-scaled by 1/8 in projection. P round-trips via per-warp smem rows.
// ---------------------------------------------------------------------------
#define ATTN_SMEM_BYTES ((128 + 64 + 64 + 128) * 144)   // 55296

__global__ __launch_bounds__(256)
void attn_h(const float* __restrict__ sel)
{
    extern __shared__ char smx[];
    char* sQ = smx;                       // [128][144B]
    char* sK = smx + 128 * 144;           // [64][144B]  [seq][e]
    char* sV = sK + 64 * 144;             // [64][144B]  [seq][e]
    char* sP = sV + 64 * 144;             // [128][144B]

    int tid = threadIdx.x, lane = tid & 31, wid = tid >> 5;
    int g = lane >> 2, q4 = lane & 3;
    int bh = blockIdx.y, b = bh >> 4, h = bh & 15, qt = blockIdx.x;

    uint32_t sQ32 = (uint32_t)__cvta_generic_to_shared(sQ);
    uint32_t sK32 = (uint32_t)__cvta_generic_to_shared(sK);
    uint32_t sV32 = (uint32_t)__cvta_generic_to_shared(sV);
    uint32_t sP32 = (uint32_t)__cvta_generic_to_shared(sP);

    // head weight = softmax(sel)[h]
    float hm = -1e30f;
#pragma unroll
    for (int i = 0; i < HH; i++) hm = fmaxf(hm, sel[i]);
    float hsum = 0.f;
#pragma unroll
    for (int i = 0; i < HH; i++) hsum += __expf(sel[i] - hm);
    float hw = __expf(sel[h] - hm) / hsum;

    const __half* Qg = g_Q + ((size_t)bh * SS + qt * 128) * EE;
    const __half* Kg = g_K + (size_t)bh * SS * EE;
    const __half* Vg = g_V + (size_t)bh * SS * EE;

    // load Q tile [128][64] half
#pragma unroll
    for (int j = 0; j < 4; j++) {
        int cid = tid + j * 256;
        int r = cid >> 3, ch = cid & 7;
        uint4 v = *(const uint4*)(Qg + (size_t)r * EE + ch * 8);
        *(uint4*)(sQ + r * 144 + ch * 16) = v;
    }

    int mrow = wid * 16;

    // per-thread fragment addresses
    uint32_t qAddr = sQ32 + (mrow + (lane & 15)) * 144 + (lane >> 4) * 16;   // + ks*32
    uint32_t pAddr = sP32 + (mrow + (lane & 15)) * 144 + (lane >> 4) * 16;   // + ks*32
    // K b-frag (non-trans on [n][k]): row = nt*16 + (lane&7) + ((lane>>4)<<3), chunk = ks*2 + ((lane>>3)&1)
    uint32_t kAddrBase = sK32 + ((lane & 7) + ((lane >> 4) << 3)) * 144 + ((lane >> 3) & 1) * 16;
    // V b-frag (trans on [k][n]): row = ks*16 + (lane&15), chunk = nt*2 + (lane>>4)
    uint32_t vAddrBase = sV32 + (lane & 15) * 144 + (lane >> 4) * 16;

    float o[8][4] = {};
    float m0r = -1e30f, m1r = -1e30f, l0r = 0.f, l1r = 0.f;

    for (int kt = 0; kt < SS / 64; kt++) {
        __syncthreads();   // prior tile's K/V/P reads done
#pragma unroll
        for (int j = 0; j < 2; j++) {
            int cid = tid + j * 256;
            int r = cid >> 3, ch = cid & 7;
            uint4 kv = *(const uint4*)(Kg + (size_t)(kt * 64 + r) * EE + ch * 8);
            uint4 vv = *(const uint4*)(Vg + (size_t)(kt * 64 + r) * EE + ch * 8);
            *(uint4*)(sK + r * 144 + ch * 16) = kv;
            *(uint4*)(sV + r * 144 + ch * 16) = vv;
        }
        __syncthreads();

        // S = Q K^T : 16 rows x 64 cols, k-dim = 64 (4 k16 steps)
        float s[8][4] = {};
#pragma unroll
        for (int ks = 0; ks < 4; ks++) {
            uint32_t a[4];
            ldsm_x4(a, qAddr + ks * 32);
#pragma unroll
            for (int nt = 0; nt < 4; nt++) {
                uint32_t bfr[4];
                ldsm_x4(bfr, kAddrBase + (nt * 16) * 144 + ks * 32);
                mma_f16(s[nt * 2 + 0], a, &bfr[0]);
                mma_f16(s[nt * 2 + 1], a, &bfr[2]);
            }
        }

        // online softmax (rows g, g+8; reduce over quad lanes)
        float mx0 = -1e30f, mx1 = -1e30f;
#pragma unroll
        for (int sn = 0; sn < 8; sn++) {
            mx0 = fmaxf(mx0, fmaxf(s[sn][0], s[sn][1]));
            mx1 = fmaxf(mx1, fmaxf(s[sn][2], s[sn][3]));
        }
        mx0 = fmaxf(mx0, __shfl_xor_sync(0xffffffffu, mx0, 1));
        mx0 = fmaxf(mx0, __shfl_xor_sync(0xffffffffu, mx0, 2));
        mx1 = fmaxf(mx1, __shfl_xor_sync(0xffffffffu, mx1, 1));
        mx1 = fmaxf(mx1, __shfl_xor_sync(0xffffffffu, mx1, 2));
        float nm0 = fmaxf(m0r, mx0), nm1 = fmaxf(m1r, mx1);
        float al0 = __expf(m0r - nm0), al1 = __expf(m1r - nm1);
        m0r = nm0; m1r = nm1;
        float sum0 = 0.f, sum1 = 0.f;
#pragma unroll
        for (int sn = 0; sn < 8; sn++) {
            s[sn][0] = __expf(s[sn][0] - nm0); s[sn][1] = __expf(s[sn][1] - nm0);
            s[sn][2] = __expf(s[sn][2] - nm1); s[sn][3] = __expf(s[sn][3] - nm1);
            sum0 += s[sn][0] + s[sn][1];
            sum1 += s[sn][2] + s[sn][3];
        }
        sum0 += __shfl_xor_sync(0xffffffffu, sum0, 1);
        sum0 += __shfl_xor_sync(0xffffffffu, sum0, 2);
        sum1 += __shfl_xor_sync(0xffffffffu, sum1, 1);
        sum1 += __shfl_xor_sync(0xffffffffu, sum1, 2);
        l0r = l0r * al0 + sum0;
        l1r = l1r * al1 + sum1;

        // rescale O, write P (half) to this warp's rows
#pragma unroll
        for (int sn = 0; sn < 8; sn++) {
            o[sn][0] *= al0; o[sn][1] *= al0;
            o[sn][2] *= al1; o[sn][3] *= al1;
            int c = sn * 8 + q4 * 2;
            __half2 p0 = __floats2half2_rn(s[sn][0], s[sn][1]);
            __half2 p1 = __floats2half2_rn(s[sn][2], s[sn][3]);
            *(__half2*)(sP + (mrow + g) * 144 + c * 2) = p0;
            *(__half2*)(sP + (mrow + g + 8) * 144 + c * 2) = p1;
        }
        __syncwarp();

        // O += P V : k-dim = 64 seq (4 k16 steps), n = 64 e-cols
#pragma unroll
        for (int ks = 0; ks < 4; ks++) {
            uint32_t a[4];
            ldsm_x4(a, pAddr + ks * 32);
#pragma unroll
            for (int nt = 0; nt < 4; nt++) {
                uint32_t bfr[4];
                ldsm_x4_t(bfr, vAddrBase + (ks * 16) * 144 + nt * 32);
                mma_f16(o[nt * 2 + 0], a, &bfr[0]);
                mma_f16(o[nt * 2 + 1], a, &bfr[2]);
            }
        }
    }

    // epilogue: normalize, gate, write ctx [B,S,H*E] (half)
    float inv0 = hw / l0r, inv1 = hw / l1r;
#pragma unroll
    for (int sn = 0; sn < 8; sn++) {
        int e = sn * 8 + q4 * 2;
        int r0 = qt * 128 + mrow + g, r1 = r0 + 8;
        __half2 x0 = __floats2half2_rn(o[sn][0] * inv0, o[sn][1] * inv0);
        __half2 x1 = __floats2half2_rn(o[sn][2] * inv1, o[sn][3] * inv1);
        *(__half2*)&g_ctx[((size_t)(b * SS + r0) * HH + h) * EE + e] = x0;
        *(__half2*)&g_ctx[((size_t)(b * SS + r1) * HH + h) * EE + e] = x1;
    }
}

// ---------------------------------------------------------------------------
extern "C" void kernel_launch(void* const* d_in, const int* in_sizes, int n_in,
                              void* d_out, int out_size)
{
    (void)in_sizes; (void)n_in; (void)out_size;
    const float* query = (const float*)d_in[0];
    const float* key   = (const float*)d_in[1];
    const float* value = (const float*)d_in[2];
    const float* Wq    = (const float*)d_in[3];
    const float* bq    = (const float*)d_in[4];
    const float* Wk    = (const float*)d_in[5];
    const float* bk    = (const float*)d_in[6];
    const float* Wv    = (const float*)d_in[7];
    const float* bv    = (const float*)d_in[8];
    const float* Wo    = (const float*)d_in[9];
    const float* bo    = (const float*)d_in[10];
    const float* sel   = (const float*)d_in[11];
    float* out = (float*)d_out;

    cudaFuncSetAttribute(attn_h, cudaFuncAttributeMaxDynamicSharedMemorySize,
                         ATTN_SMEM_BYTES);

    dim3 gblk(256);
    dim3 ggrid(DD / 128, (BB * SS) / 128);  // 8 x 64

    proj_gemm_h<<<ggrid, gblk>>>(query, Wq, bq, 0, 0.125f);  // scale folded into Q
    proj_gemm_h<<<ggrid, gblk>>>(key,   Wk, bk, 1, 1.0f);
    proj_gemm_h<<<ggrid, gblk>>>(value, Wv, bv, 2, 1.0f);

    attn_h<<<dim3(SS / 128, BB * HH), 256, ATTN_SMEM_BYTES>>>(sel);

    out_gemm_h<<<ggrid, gblk>>>(Wo, bo, out);
}